// round 1
// baseline (speedup 1.0000x reference)
#include <cuda_runtime.h>
#include <cstdint>
#include <cstddef>

typedef unsigned long long ull;

#define BATCH   32
#define T_STEPS 2048
#define HID     256
#define BT      (BATCH * T_STEPS)         // 65536
#define GCOLS   768                       // [r(256) | z(256) | n(256)] input-side gates

// Scratch for input-side projections: (BT, 768) fp32 = 192 MB (static, no cudaMalloc)
__device__ float g_xproj[(size_t)BT * GCOLS];

// ---------------------------------------------------------------------------
// helpers
// ---------------------------------------------------------------------------
__device__ __forceinline__ void ffma2(ull& d, ull a, ull b) {
    // packed dual-fp32 FMA (Blackwell): d.lo += a.lo*b.lo ; d.hi += a.hi*b.hi
    asm("fma.rn.f32x2 %0, %1, %2, %0;" : "+l"(d) : "l"(a), "l"(b));
}

__device__ __forceinline__ void st_cluster_f32(uint32_t addr, uint32_t rank, float v) {
    uint32_t ra;
    asm volatile("mapa.shared::cluster.u32 %0, %1, %2;" : "=r"(ra) : "r"(addr), "r"(rank));
    asm volatile("st.shared::cluster.f32 [%0], %1;" :: "r"(ra), "f"(v) : "memory");
}

// ---------------------------------------------------------------------------
// Kernel 1: input projection GEMM
//   out[m, n] = sum_k x[m,k] * Wcat[n,k] + bcat[n]
//   Wcat rows: n<512 -> W_irz[n], n>=512 -> W_in[n-512]
// Tile: M=64 x N=128 x K=256 (full K in smem). 128 threads, 8x8 reg tile,
// k-pairs packed into f32x2 accumulators.
// ---------------------------------------------------------------------------
#define PROJ_SMEM_BYTES ((64*256 + 128*260) * 4)   // As 64KB + Bs (pitch 260) 130KB = 198656 B

__global__ void __launch_bounds__(128, 1) proj_kernel(
    const float* __restrict__ x,
    const float* __restrict__ W_irz, const float* __restrict__ b_irz,
    const float* __restrict__ W_in,  const float* __restrict__ b_in)
{
    extern __shared__ float smem[];
    float* As = smem;               // [64][256] (same layout as global slice)
    float* Bs = smem + 64 * 256;    // [128] rows, pitch 260 floats (conflict padding)

    const int tid = threadIdx.x;
    const int m0 = blockIdx.x * 64;
    const int n0 = blockIdx.y * 128;

    const float* Wsrc; const float* bsrc;
    if (n0 < 512) { Wsrc = W_irz + (size_t)n0 * 256;        bsrc = b_irz + n0; }
    else          { Wsrc = W_in  + (size_t)(n0 - 512) * 256; bsrc = b_in + (n0 - 512); }

    // ---- load tiles (float4, coalesced) ----
    {
        const float4* xg = (const float4*)(x + (size_t)m0 * 256);
        float4* As4 = (float4*)As;
        #pragma unroll
        for (int it = 0; it < 32; it++) {
            int idx = it * 128 + tid;            // 64 rows x 64 f4
            As4[idx] = xg[idx];
        }
        const float4* wg = (const float4*)Wsrc;
        #pragma unroll
        for (int it = 0; it < 64; it++) {
            int idx = it * 128 + tid;            // 128 rows x 64 f4
            int n = idx >> 6, k4 = idx & 63;
            *(float4*)(Bs + n * 260 + (k4 << 2)) = wg[idx];
        }
    }
    __syncthreads();

    const int lane = tid & 31, warp = tid >> 5;
    const int cg = lane & 15;        // 16 col-groups
    const int rg2 = lane >> 4;       // 2 row-groups per warp
    const int rglob = warp * 2 + rg2; // 0..7

    ull acc[64];
    #pragma unroll
    for (int i = 0; i < 64; i++) acc[i] = 0ull;

    const ull* Au = (const ull*)As;  // row m: m*128 ull
    const ull* Bu = (const ull*)Bs;  // row c: c*130 ull

    int aoff[8], boff[8];
    #pragma unroll
    for (int i = 0; i < 8; i++) aoff[i] = (rglob + 8 * i) * 128;
    #pragma unroll
    for (int j = 0; j < 8; j++) boff[j] = (cg + 16 * j) * 130;

    #pragma unroll 2
    for (int kk = 0; kk < 128; kk++) {       // kk = k-pair index
        ull a2[8], b2[8];
        #pragma unroll
        for (int i = 0; i < 8; i++) a2[i] = Au[aoff[i] + kk];
        #pragma unroll
        for (int j = 0; j < 8; j++) b2[j] = Bu[boff[j] + kk];
        #pragma unroll
        for (int i = 0; i < 8; i++)
            #pragma unroll
            for (int j = 0; j < 8; j++)
                ffma2(acc[i * 8 + j], a2[i], b2[j]);
    }

    // ---- epilogue: horizontal add of the k-pair partials + bias ----
    float bias[8];
    #pragma unroll
    for (int j = 0; j < 8; j++) bias[j] = bsrc[cg + 16 * j];

    #pragma unroll
    for (int i = 0; i < 8; i++) {
        int m = rglob + 8 * i;
        float* orow = g_xproj + (size_t)(m0 + m) * GCOLS + n0;
        #pragma unroll
        for (int j = 0; j < 8; j++) {
            union { ull u; float f[2]; } v; v.u = acc[i * 8 + j];
            orow[cg + 16 * j] = v.f[0] + v.f[1] + bias[j];
        }
    }
}

// ---------------------------------------------------------------------------
// Kernel 2: persistent GRU recurrence.
// Cluster of 4 CTAs per batch element (grid 128, block 384).
// CTA rank c owns hidden units [c*64, c*64+64): 192 gate rows x 256 k,
// weights register-resident (2 threads per row, 64 ull = 128 floats each).
// h double-buffered in smem, broadcast to cluster peers via DSMEM stores,
// one barrier.cluster per step.
// ---------------------------------------------------------------------------
__global__ void __cluster_dims__(4, 1, 1) __launch_bounds__(384, 1)
gru_kernel(const float* __restrict__ h0,
           const float* __restrict__ W_hrz, const float* __restrict__ b_hrz,
           const float* __restrict__ W_hn,  const float* __restrict__ b_hn,
           float* __restrict__ out, int write_hn)
{
    __shared__ __align__(16) float hbuf[2][HID];
    __shared__ float gsum[192];

    const int tid  = threadIdx.x;
    const int b    = blockIdx.x >> 2;
    const int rank = blockIdx.x & 3;
    const int j0   = rank * 64;
    const int ro   = tid >> 1;    // gate-row 0..191
    const int hf   = tid & 1;     // k-half

    // ---- register-resident weights: 128 floats = 64 packed f32x2 ----
    ull w[64];
    {
        const float* src;
        if (ro < 64)       src = W_hrz + (size_t)(j0 + ro) * 256;                 // r rows
        else if (ro < 128) src = W_hrz + (size_t)(256 + j0 + (ro - 64)) * 256;    // z rows
        else               src = W_hn  + (size_t)(j0 + (ro - 128)) * 256;         // n rows
        const ull* ws = (const ull*)src + hf * 64;
        #pragma unroll
        for (int i = 0; i < 64; i++) w[i] = ws[i];
    }

    float bhr = 0.f, bhz = 0.f, bhn = 0.f;
    if (tid < 64) {
        bhr = b_hrz[j0 + tid];
        bhz = b_hrz[256 + j0 + tid];
        bhn = b_hn[j0 + tid];
    }
    if (tid < HID) hbuf[0][tid] = h0[(size_t)b * HID + tid];
    __syncthreads();
    asm volatile("barrier.cluster.arrive.aligned;" ::: "memory");
    asm volatile("barrier.cluster.wait.aligned;"  ::: "memory");

    const float* xbase = g_xproj + (size_t)b * T_STEPS * GCOLS;
    float* obase = out + (size_t)b * T_STEPS * HID;

    // prefetch x-side gate inputs for t=0
    float xr = 0.f, xz = 0.f, xn = 0.f;
    if (tid < 64) {
        xr = xbase[j0 + tid];
        xz = xbase[256 + j0 + tid];
        xn = xbase[512 + j0 + tid];
    }

    for (int t = 0; t < T_STEPS; t++) {
        const int par = t & 1;

        // ---- matvec: this thread's 128-k half of its gate row ----
        ull acc0 = 0ull, acc1 = 0ull;
        const float4* h4 = (const float4*)hbuf[par] + hf * 32;
        #pragma unroll
        for (int i = 0; i < 32; i++) {
            union { float4 f; ull u[2]; } hv;
            hv.f = h4[i];
            ffma2(acc0, w[2 * i],     hv.u[0]);
            ffma2(acc1, w[2 * i + 1], hv.u[1]);
        }
        union { ull u; float f[2]; } ua, ub;
        ua.u = acc0; ub.u = acc1;
        float s = (ua.f[0] + ua.f[1]) + (ub.f[0] + ub.f[1]);
        s += __shfl_xor_sync(0xffffffffu, s, 1);   // combine the two k-halves
        if (hf == 0) gsum[ro] = s;

        // prefetch next step's x while the barrier drains
        float nxr = xr, nxz = xz, nxn = xn;
        if (tid < 64 && t + 1 < T_STEPS) {
            const float* p = xbase + (size_t)(t + 1) * GCOLS;
            nxr = p[j0 + tid]; nxz = p[256 + j0 + tid]; nxn = p[512 + j0 + tid];
        }
        __syncthreads();

        // ---- epilogue: 64 threads finalize their hidden units ----
        if (tid < 64) {
            const int j = tid;
            float rp = gsum[j]      + bhr + xr;
            float zp = gsum[64 + j] + bhz + xz;
            float r = __fdividef(1.0f, 1.0f + __expf(-rp));
            float z = __fdividef(1.0f, 1.0f + __expf(-zp));
            float npre = xn + r * (gsum[128 + j] + bhn);
            float e = __expf(-2.0f * npre);
            float n = __fdividef(1.0f - e, 1.0f + e);   // tanh
            float hold = hbuf[par][j0 + j];
            float hnew = z * (hold - n) + n;            // (1-z)*n + z*h

            obase[(size_t)t * HID + j0 + j] = hnew;

            uint32_t sa = (uint32_t)__cvta_generic_to_shared(&hbuf[par ^ 1][j0 + j]);
            st_cluster_f32(sa, 0, hnew);
            st_cluster_f32(sa, 1, hnew);
            st_cluster_f32(sa, 2, hnew);
            st_cluster_f32(sa, 3, hnew);

            if (write_hn && t == T_STEPS - 1)
                out[(size_t)BATCH * T_STEPS * HID + (size_t)b * HID + j0 + j] = hnew;
        }
        xr = nxr; xz = nxz; xn = nxn;

        // release own writes / acquire peers' writes; single sync per step
        asm volatile("barrier.cluster.arrive.aligned;" ::: "memory");
        asm volatile("barrier.cluster.wait.aligned;"  ::: "memory");
    }
}

// ---------------------------------------------------------------------------
// launch
// ---------------------------------------------------------------------------
extern "C" void kernel_launch(void* const* d_in, const int* in_sizes, int n_in,
                              void* d_out, int out_size)
{
    (void)in_sizes; (void)n_in;
    const float* x     = (const float*)d_in[0];
    const float* h0    = (const float*)d_in[1];
    const float* W_irz = (const float*)d_in[2];
    const float* b_irz = (const float*)d_in[3];
    const float* W_hrz = (const float*)d_in[4];
    const float* b_hrz = (const float*)d_in[5];
    const float* W_in  = (const float*)d_in[6];
    const float* b_in  = (const float*)d_in[7];
    const float* W_hn  = (const float*)d_in[8];
    const float* b_hn  = (const float*)d_in[9];
    float* out = (float*)d_out;

    cudaFuncSetAttribute(proj_kernel, cudaFuncAttributeMaxDynamicSharedMemorySize,
                         PROJ_SMEM_BYTES);
    proj_kernel<<<dim3(BT / 64, GCOLS / 128, 1), 128, PROJ_SMEM_BYTES>>>(
        x, W_irz, b_irz, W_in, b_in);

    const long long need_hn = (long long)BATCH * T_STEPS * HID + (long long)BATCH * HID;
    int write_hn = ((long long)out_size >= need_hn) ? 1 : 0;
    gru_kernel<<<BATCH * 4, 384>>>(h0, W_hrz, b_hrz, W_hn, b_hn, out, write_hn);
}